// round 6
// baseline (speedup 1.0000x reference)
#include <cuda_runtime.h>
#include <math.h>

#define NPIX 256
#define TPB 352      // 11 warps; 143 blocks => exactly 1 wave on 148 SMs
#define YTILE 32     // rows staged in SMEM per tile (32 KB)

typedef unsigned long long ull;

// Transposed preprocessed image: d_imgT[x * NPIX + y]
__device__ __align__(16) float d_imgT[NPIX * NPIX];

// ---- packed f32x2 helpers (Blackwell FFMA2 path) ----
__device__ __forceinline__ ull pack2(float lo, float hi) {
    ull r; asm("mov.b64 %0, {%1,%2};" : "=l"(r) : "f"(lo), "f"(hi)); return r;
}
__device__ __forceinline__ void unpack2(ull v, float& lo, float& hi) {
    asm("mov.b64 {%0,%1}, %2;" : "=f"(lo), "=f"(hi) : "l"(v));
}
#define FMA2(d, a, b, c) asm("fma.rn.f32x2 %0, %1, %2, %3;" : "=l"(d) : "l"(a), "l"(b), "l"(c))
#define MUL2(d, a, b)    asm("mul.rn.f32x2 %0, %1, %2;"     : "=l"(d) : "l"(a), "l"(b))

// Kernel 1: img = HannConv3x3(softplus(base)), zero-padded SAME, stored TRANSPOSED.
__global__ void prep_kernel(const float* __restrict__ base) {
    int idx = blockIdx.x * blockDim.x + threadIdx.x;
    if (idx >= NPIX * NPIX) return;
    int px = idx & (NPIX - 1);
    int py = idx >> 8;
    const float w[3] = {0.25f, 0.5f, 0.25f};
    float acc = 0.f;
#pragma unroll
    for (int dy = -1; dy <= 1; ++dy) {
#pragma unroll
        for (int dx = -1; dx <= 1; ++dx) {
            int yy = py + dy, xx = px + dx;
            if (yy >= 0 && yy < NPIX && xx >= 0 && xx < NPIX) {
                float v = base[yy * NPIX + xx];
                float sp = fmaxf(v, 0.f) + log1pf(expf(-fabsf(v)));  // stable softplus
                acc += w[dy + 1] * w[dx + 1] * sp;
            }
        }
    }
    d_imgT[px * NPIX + py] = acc;   // transposed store
}

// Load a group of 4 x-pixels (4 rows each) into 8 packed ulls.
#define LOADG(dst, pxbase)                                                     \
    {                                                                          \
        _Pragma("unroll")                                                      \
        for (int t_ = 0; t_ < 4; ++t_) {                                       \
            const double2 dd_ = *(const double2*)(stp + ((pxbase) + t_) * (YTILE * 4)); \
            dst[2 * t_ + 0] = __double_as_longlong(dd_.x);                     \
            dst[2 * t_ + 1] = __double_as_longlong(dd_.y);                     \
        }                                                                      \
    }

// Kernel 2: exact type-2 NUDFT, packed f32x2 datapath + double-buffered LDS prefetch.
// vis[k] = cell^2 * e^{+2pi*i*128*(fu+fv)} * sum_y e^{-2pi*i*fv*y} sum_x img[y,x] e^{-2pi*i*fu*x}
__global__ void __launch_bounds__(TPB)
vis_kernel(const float* __restrict__ uu,
           const float* __restrict__ vv,
           float* __restrict__ out, int nvis, int mode) {
    // st[x][j]: YTILE y-values contiguous per x -> double2 load = rows j0..j0+3 at x
    __shared__ __align__(16) float st[NPIX][YTILE];

    const int k = blockIdx.x * TPB + threadIdx.x;
    const float ARCSEC_F = (float)(M_PI / 180.0 / 3600.0);
    const float cell_rad = 0.005f * ARCSEC_F;

    float fu = 0.f, fv = 0.f;
    if (k < nvis) {
        fu = (uu[k] * 1e3f) * cell_rad;   // cycles per pixel in x, |fu| <= 0.25
        fv = (vv[k] * 1e3f) * cell_rad;
    }

    // x-twiddle table wt[r] = w^r, r=0..15, broadcast-packed. w = exp(-2*pi*i*fu).
    float wur, wui; sincospif(-2.f * fu, &wui, &wur);
    ull wtr2[16], wti2[16];
    {
        float tr = 1.f, ti = 0.f;
        wtr2[0] = pack2(1.f, 1.f); wti2[0] = pack2(0.f, 0.f);
#pragma unroll
        for (int r = 1; r < 16; ++r) {
            float nr = tr * wur - ti * wui;
            float ni = tr * wui + ti * wur;
            tr = nr; ti = ni;
            wtr2[r] = pack2(tr, tr); wti2[r] = pack2(ti, ti);
        }
    }
    // W16 = w^16 (exact seed)
    float W16r, W16i; sincospif(-32.f * fu, &W16i, &W16r);
    const ull W16r2  = pack2(W16r, W16r);
    const ull W16i2  = pack2(W16i, W16i);
    const ull nW16i2 = pack2(-W16i, -W16i);

    // y-phase steps
    float wvr, wvi;   sincospif(-2.f * fv, &wvi, &wvr);   // wv = exp(-2*pi*i*fv)
    float Wv4r, Wv4i; sincospif(-8.f * fv, &Wv4i, &Wv4r); // wv^4
    const ull Wv4r2  = pack2(Wv4r, Wv4r);
    const ull Wv4i2  = pack2(Wv4i, Wv4i);
    const ull nWv4i2 = pack2(-Wv4i, -Wv4i);

    const ull Z2 = pack2(0.f, 0.f);
    ull visR0 = Z2, visI0 = Z2, visR1 = Z2, visI1 = Z2;

    for (int y0 = 0; y0 < NPIX; y0 += YTILE) {
        __syncthreads();
        // Stage: st[x][j] = imgT[x][y0+j]; contiguous global float4 per (x, 4j)
        for (int i = threadIdx.x; i < NPIX * (YTILE / 4); i += TPB) {
            int x = i >> 3, c = i & 7;
            float4 v = *(const float4*)&d_imgT[x * NPIX + y0 + 4 * c];
            *(float4*)&st[x][4 * c] = v;
        }
        __syncthreads();

        // b seeds for this tile: b_y = exp(-2*pi*i*fv*y), exact reseed (no drift)
        float b0r, b0i; sincospif(-2.f * fv * (float)y0, &b0i, &b0r);
        float b1r = b0r * wvr - b0i * wvi, b1i = b0r * wvi + b0i * wvr;
        float b2r = b1r * wvr - b1i * wvi, b2i = b1r * wvi + b1i * wvr;
        float b3r = b2r * wvr - b2i * wvi, b3i = b2r * wvi + b2i * wvr;
        ull bR0 = pack2(b0r, b1r), bI0 = pack2(b0i, b1i), nbI0 = pack2(-b0i, -b1i);
        ull bR1 = pack2(b2r, b3r), bI1 = pack2(b2i, b3i), nbI1 = pack2(-b2i, -b3i);

        for (int j0 = 0; j0 < YTILE; j0 += 4) {     // 4 rows per pass
            ull AR2 = pack2(1.f, 1.f), AI2 = Z2, nAI2 = Z2;   // A = W16^q
            ull rowR0 = Z2, rowI0 = Z2, rowR1 = Z2, rowI1 = Z2;
            const char* stp = (const char*)&st[0][j0];

            // Double-buffered prefetch pipeline: load group g+2 while computing g.
            ull bufA[8], bufB[8];
            LOADG(bufA, 0);
            LOADG(bufB, 4);
            int px = 8;

            for (int q = 0; q < 16; ++q) {          // rolled: 16-entry table stays static-indexed
                ull pr0 = Z2, pi0 = Z2, pr1 = Z2, pi1 = Z2;
#pragma unroll
                for (int g = 0; g < 4; ++g) {       // 4 groups of 4 pixels
                    ull* cur = (g & 1) ? bufB : bufA;
#pragma unroll
                    for (int t = 0; t < 4; ++t) {
                        const int r = g * 4 + t;
                        const ull p01 = cur[2 * t + 0];
                        const ull p23 = cur[2 * t + 1];
                        FMA2(pr0, p01, wtr2[r], pr0); FMA2(pi0, p01, wti2[r], pi0);
                        FMA2(pr1, p23, wtr2[r], pr1); FMA2(pi1, p23, wti2[r], pi1);
                    }
                    if (px < NPIX) LOADG(cur, px);  // prefetch 2 groups ahead
                    px += 4;
                }
                // row += p * A   (complex, A broadcast in both lanes)
                FMA2(rowR0, pr0, AR2, rowR0); FMA2(rowR0, pi0, nAI2, rowR0);
                FMA2(rowI0, pr0, AI2, rowI0); FMA2(rowI0, pi0, AR2, rowI0);
                FMA2(rowR1, pr1, AR2, rowR1); FMA2(rowR1, pi1, nAI2, rowR1);
                FMA2(rowI1, pr1, AI2, rowI1); FMA2(rowI1, pi1, AR2, rowI1);
                // A *= W16
                ull t0, t1, t2, ARn, AIn, nAIn;
                MUL2(t0, nAI2, W16i2); FMA2(ARn,  AR2, W16r2,  t0);
                MUL2(t1, AI2,  W16r2); FMA2(AIn,  AR2, W16i2,  t1);
                MUL2(t2, nAI2, W16r2); FMA2(nAIn, AR2, nW16i2, t2);
                AR2 = ARn; AI2 = AIn; nAI2 = nAIn;
            }
            // vis += row * b  (lane-wise complex; lanes carry adjacent rows)
            FMA2(visR0, rowR0, bR0, visR0); FMA2(visR0, rowI0, nbI0, visR0);
            FMA2(visI0, rowR0, bI0, visI0); FMA2(visI0, rowI0, bR0, visI0);
            FMA2(visR1, rowR1, bR1, visR1); FMA2(visR1, rowI1, nbI1, visR1);
            FMA2(visI1, rowR1, bI1, visI1); FMA2(visI1, rowI1, bR1, visI1);
            // b *= wv^4 (both pairs)
            ull u0, u1, u2, nR, nI, nnI;
            MUL2(u0, nbI0, Wv4i2); FMA2(nR,  bR0, Wv4r2,  u0);
            MUL2(u1, bI0,  Wv4r2); FMA2(nI,  bR0, Wv4i2,  u1);
            MUL2(u2, nbI0, Wv4r2); FMA2(nnI, bR0, nWv4i2, u2);
            bR0 = nR; bI0 = nI; nbI0 = nnI;
            MUL2(u0, nbI1, Wv4i2); FMA2(nR,  bR1, Wv4r2,  u0);
            MUL2(u1, bI1,  Wv4r2); FMA2(nI,  bR1, Wv4i2,  u1);
            MUL2(u2, nbI1, Wv4r2); FMA2(nnI, bR1, nWv4i2, u2);
            bR1 = nR; bI1 = nI; nbI1 = nnI;
        }
    }

    if (k < nvis) {
        float a0, a1, c0, c1, e0, e1, g0, g1;
        unpack2(visR0, a0, a1); unpack2(visR1, c0, c1);
        unpack2(visI0, e0, e1); unpack2(visI1, g0, g1);
        float visr = (a0 + a1) + (c0 + c1);
        float visi = (e0 + e1) + (g0 + g1);
        // centering phase: exp(+2*pi*i*128*(fu+fv)) — exact, applied once
        float Sr, Si; sincospif(256.f * fu + 256.f * fv, &Si, &Sr);
        float c2 = cell_rad * cell_rad;
        float orr = (visr * Sr - visi * Si) * c2;
        float oii = (visr * Si + visi * Sr) * c2;
        if (mode == 0) {
            out[k] = orr;
        } else {
            out[2 * k + 0] = orr;
            out[2 * k + 1] = oii;
        }
    }
}

extern "C" void kernel_launch(void* const* d_in, const int* in_sizes, int n_in,
                              void* d_out, int out_size) {
    // Input mapping by size: image is uniquely the 65536-element input;
    // the remaining two, in order, are uu then vv.
    int img_i = -1;
    for (int i = 0; i < n_in; ++i)
        if (in_sizes[i] == NPIX * NPIX) { img_i = i; break; }
    if (img_i < 0) img_i = 0;
    int uv_idx[2]; int c = 0;
    for (int i = 0; i < n_in && c < 2; ++i)
        if (i != img_i) uv_idx[c++] = i;

    const float* base = (const float*)d_in[img_i];
    const float* uu   = (const float*)d_in[uv_idx[0]];
    const float* vv   = (const float*)d_in[uv_idx[1]];
    float* out = (float*)d_out;
    const int nvis = in_sizes[uv_idx[0]];

    // Same output-mode logic that passed in R4/R5.
    int mode = (out_size >= 2 * nvis) ? 1 : 0;

    prep_kernel<<<(NPIX * NPIX + 255) / 256, 256>>>(base);
    int blocks = (nvis + TPB - 1) / TPB;   // 143 for nvis=50000 -> single wave
    vis_kernel<<<blocks, TPB>>>(uu, vv, out, nvis, mode);
}

// round 7
// speedup vs baseline: 1.1922x; 1.1922x over previous
#include <cuda_runtime.h>
#include <math.h>

#define NPIX 256
#define TPB 352      // 11 warps; grid (143,2) => 286 CTAs, 2/SM, single wave
#define YTILE 32     // rows staged in SMEM per tile (32 KB)
#define KMAX (143 * TPB)

typedef unsigned long long ull;

// Transposed preprocessed image: d_imgT[x * NPIX + y]
__device__ __align__(16) float d_imgT[NPIX * NPIX];
// Partial sums per y-half: d_part[half][k] = (re, im) before centering/scale
__device__ __align__(16) float2 d_part[2][KMAX];

// ---- packed f32x2 helpers (Blackwell FFMA2 path) ----
__device__ __forceinline__ ull pack2(float lo, float hi) {
    ull r; asm("mov.b64 %0, {%1,%2};" : "=l"(r) : "f"(lo), "f"(hi)); return r;
}
__device__ __forceinline__ void unpack2(ull v, float& lo, float& hi) {
    asm("mov.b64 {%0,%1}, %2;" : "=f"(lo), "=f"(hi) : "l"(v));
}
#define FMA2(d, a, b, c) asm("fma.rn.f32x2 %0, %1, %2, %3;" : "=l"(d) : "l"(a), "l"(b), "l"(c))
#define MUL2(d, a, b)    asm("mul.rn.f32x2 %0, %1, %2;"     : "=l"(d) : "l"(a), "l"(b))

// Kernel 1: img = HannConv3x3(softplus(base)), zero-padded SAME, stored TRANSPOSED.
__global__ void prep_kernel(const float* __restrict__ base) {
    int idx = blockIdx.x * blockDim.x + threadIdx.x;
    if (idx >= NPIX * NPIX) return;
    int px = idx & (NPIX - 1);
    int py = idx >> 8;
    const float w[3] = {0.25f, 0.5f, 0.25f};
    float acc = 0.f;
#pragma unroll
    for (int dy = -1; dy <= 1; ++dy) {
#pragma unroll
        for (int dx = -1; dx <= 1; ++dx) {
            int yy = py + dy, xx = px + dx;
            if (yy >= 0 && yy < NPIX && xx >= 0 && xx < NPIX) {
                float v = base[yy * NPIX + xx];
                float sp = fmaxf(v, 0.f) + log1pf(expf(-fabsf(v)));  // stable softplus
                acc += w[dy + 1] * w[dx + 1] * sp;
            }
        }
    }
    d_imgT[px * NPIX + py] = acc;   // transposed store
}

// Kernel 2: exact type-2 NUDFT partial over one y-half (128 rows).
// d_part[half][k] = sum_{y in half} e^{-2pi*i*fv*y} sum_x img[y,x] e^{-2pi*i*fu*x}
__global__ void __launch_bounds__(TPB, 2)
vis_kernel(const float* __restrict__ uu,
           const float* __restrict__ vv, int nvis) {
    // st[x][j]: YTILE y-values contiguous per x -> double2 load = rows j0..j0+3 at x
    __shared__ __align__(16) float st[NPIX][YTILE];

    const int k = blockIdx.x * TPB + threadIdx.x;
    const int half = blockIdx.y;
    const float ARCSEC_F = (float)(M_PI / 180.0 / 3600.0);
    const float cell_rad = 0.005f * ARCSEC_F;

    float fu = 0.f, fv = 0.f;
    if (k < nvis) {
        fu = (uu[k] * 1e3f) * cell_rad;   // cycles per pixel in x, |fu| <= 0.25
        fv = (vv[k] * 1e3f) * cell_rad;
    }

    // x-twiddle table wt[r] = w^r, r=0..15, broadcast-packed. w = exp(-2*pi*i*fu).
    float wur, wui; sincospif(-2.f * fu, &wui, &wur);
    ull wtr2[16], wti2[16];
    {
        float tr = 1.f, ti = 0.f;
        wtr2[0] = pack2(1.f, 1.f); wti2[0] = pack2(0.f, 0.f);
#pragma unroll
        for (int r = 1; r < 16; ++r) {
            float nr = tr * wur - ti * wui;
            float ni = tr * wui + ti * wur;
            tr = nr; ti = ni;
            wtr2[r] = pack2(tr, tr); wti2[r] = pack2(ti, ti);
        }
    }
    // W16 = w^16 (exact seed)
    float W16r, W16i; sincospif(-32.f * fu, &W16i, &W16r);
    const ull W16r2  = pack2(W16r, W16r);
    const ull W16i2  = pack2(W16i, W16i);
    const ull nW16i2 = pack2(-W16i, -W16i);

    // y-phase steps
    float wvr, wvi;   sincospif(-2.f * fv, &wvi, &wvr);   // wv = exp(-2*pi*i*fv)
    float Wv4r, Wv4i; sincospif(-8.f * fv, &Wv4i, &Wv4r); // wv^4
    const ull Wv4r2  = pack2(Wv4r, Wv4r);
    const ull Wv4i2  = pack2(Wv4i, Wv4i);
    const ull nWv4i2 = pack2(-Wv4i, -Wv4i);

    const ull Z2 = pack2(0.f, 0.f);
    ull visR0 = Z2, visI0 = Z2, visR1 = Z2, visI1 = Z2;

    const int ybeg = half * (NPIX / 2);
    for (int y0 = ybeg; y0 < ybeg + NPIX / 2; y0 += YTILE) {
        __syncthreads();
        // Stage: st[x][j] = imgT[x][y0+j]; contiguous global float4 per (x, 4j)
        for (int i = threadIdx.x; i < NPIX * (YTILE / 4); i += TPB) {
            int x = i >> 3, c = i & 7;
            float4 v = *(const float4*)&d_imgT[x * NPIX + y0 + 4 * c];
            *(float4*)&st[x][4 * c] = v;
        }
        __syncthreads();

        // b seeds for this tile: b_y = exp(-2*pi*i*fv*y), exact reseed (no drift)
        float b0r, b0i; sincospif(-2.f * fv * (float)y0, &b0i, &b0r);
        float b1r = b0r * wvr - b0i * wvi, b1i = b0r * wvi + b0i * wvr;
        float b2r = b1r * wvr - b1i * wvi, b2i = b1r * wvi + b1i * wvr;
        float b3r = b2r * wvr - b2i * wvi, b3i = b2r * wvi + b2i * wvr;
        ull bR0 = pack2(b0r, b1r), bI0 = pack2(b0i, b1i), nbI0 = pack2(-b0i, -b1i);
        ull bR1 = pack2(b2r, b3r), bI1 = pack2(b2i, b3i), nbI1 = pack2(-b2i, -b3i);

        for (int j0 = 0; j0 < YTILE; j0 += 4) {     // 4 rows per pass
            ull AR2 = pack2(1.f, 1.f), AI2 = Z2, nAI2 = Z2;   // A = W16^q
            ull rowR0 = Z2, rowI0 = Z2, rowR1 = Z2, rowI1 = Z2;
            const char* stp = (const char*)&st[0][j0];

            for (int q = 0; q < 16; ++q) {
                ull pr0 = Z2, pi0 = Z2, pr1 = Z2, pi1 = Z2;
#pragma unroll
                for (int r = 0; r < 16; ++r) {
                    // rows (j0..j0+3) at x = 16q + r : one broadcast LDS.128
                    const double2 dd = *(const double2*)(stp + (q * 16 + r) * (YTILE * 4));
                    ull p01 = __double_as_longlong(dd.x);
                    ull p23 = __double_as_longlong(dd.y);
                    FMA2(pr0, p01, wtr2[r], pr0); FMA2(pi0, p01, wti2[r], pi0);
                    FMA2(pr1, p23, wtr2[r], pr1); FMA2(pi1, p23, wti2[r], pi1);
                }
                // row += p * A   (complex, A broadcast in both lanes)
                FMA2(rowR0, pr0, AR2, rowR0); FMA2(rowR0, pi0, nAI2, rowR0);
                FMA2(rowI0, pr0, AI2, rowI0); FMA2(rowI0, pi0, AR2, rowI0);
                FMA2(rowR1, pr1, AR2, rowR1); FMA2(rowR1, pi1, nAI2, rowR1);
                FMA2(rowI1, pr1, AI2, rowI1); FMA2(rowI1, pi1, AR2, rowI1);
                // A *= W16
                ull t0, t1, t2, ARn, AIn, nAIn;
                MUL2(t0, nAI2, W16i2); FMA2(ARn,  AR2, W16r2,  t0);
                MUL2(t1, AI2,  W16r2); FMA2(AIn,  AR2, W16i2,  t1);
                MUL2(t2, nAI2, W16r2); FMA2(nAIn, AR2, nW16i2, t2);
                AR2 = ARn; AI2 = AIn; nAI2 = nAIn;
            }
            // vis += row * b  (lane-wise complex; lanes carry adjacent rows)
            FMA2(visR0, rowR0, bR0, visR0); FMA2(visR0, rowI0, nbI0, visR0);
            FMA2(visI0, rowR0, bI0, visI0); FMA2(visI0, rowI0, bR0, visI0);
            FMA2(visR1, rowR1, bR1, visR1); FMA2(visR1, rowI1, nbI1, visR1);
            FMA2(visI1, rowR1, bI1, visI1); FMA2(visI1, rowI1, bR1, visI1);
            // b *= wv^4 (both pairs)
            ull u0, u1, u2, nR, nI, nnI;
            MUL2(u0, nbI0, Wv4i2); FMA2(nR,  bR0, Wv4r2,  u0);
            MUL2(u1, bI0,  Wv4r2); FMA2(nI,  bR0, Wv4i2,  u1);
            MUL2(u2, nbI0, Wv4r2); FMA2(nnI, bR0, nWv4i2, u2);
            bR0 = nR; bI0 = nI; nbI0 = nnI;
            MUL2(u0, nbI1, Wv4i2); FMA2(nR,  bR1, Wv4r2,  u0);
            MUL2(u1, bI1,  Wv4r2); FMA2(nI,  bR1, Wv4i2,  u1);
            MUL2(u2, nbI1, Wv4r2); FMA2(nnI, bR1, nWv4i2, u2);
            bR1 = nR; bI1 = nI; nbI1 = nnI;
        }
    }

    if (k < nvis) {
        float a0, a1, c0, c1, e0, e1, g0, g1;
        unpack2(visR0, a0, a1); unpack2(visR1, c0, c1);
        unpack2(visI0, e0, e1); unpack2(visI1, g0, g1);
        d_part[half][k] = make_float2((a0 + a1) + (c0 + c1),
                                      (e0 + e1) + (g0 + g1));
    }
}

// Kernel 3: combine halves, apply centering phase and pixel solid angle.
__global__ void combine_kernel(const float* __restrict__ uu,
                               const float* __restrict__ vv,
                               float* __restrict__ out, int nvis, int mode) {
    int k = blockIdx.x * blockDim.x + threadIdx.x;
    if (k >= nvis) return;
    const float ARCSEC_F = (float)(M_PI / 180.0 / 3600.0);
    const float cell_rad = 0.005f * ARCSEC_F;
    float fu = (uu[k] * 1e3f) * cell_rad;
    float fv = (vv[k] * 1e3f) * cell_rad;
    float2 p0 = d_part[0][k];
    float2 p1 = d_part[1][k];
    float visr = p0.x + p1.x;
    float visi = p0.y + p1.y;
    // centering phase: exp(+2*pi*i*128*(fu+fv)) — exact, applied once
    float Sr, Si; sincospif(256.f * fu + 256.f * fv, &Si, &Sr);
    float c2 = cell_rad * cell_rad;
    float orr = (visr * Sr - visi * Si) * c2;
    float oii = (visr * Si + visi * Sr) * c2;
    if (mode == 0) {
        out[k] = orr;
    } else {
        out[2 * k + 0] = orr;
        out[2 * k + 1] = oii;
    }
}

extern "C" void kernel_launch(void* const* d_in, const int* in_sizes, int n_in,
                              void* d_out, int out_size) {
    // Input mapping by size: image is uniquely the 65536-element input;
    // the remaining two, in order, are uu then vv.
    int img_i = -1;
    for (int i = 0; i < n_in; ++i)
        if (in_sizes[i] == NPIX * NPIX) { img_i = i; break; }
    if (img_i < 0) img_i = 0;
    int uv_idx[2]; int c = 0;
    for (int i = 0; i < n_in && c < 2; ++i)
        if (i != img_i) uv_idx[c++] = i;

    const float* base = (const float*)d_in[img_i];
    const float* uu   = (const float*)d_in[uv_idx[0]];
    const float* vv   = (const float*)d_in[uv_idx[1]];
    float* out = (float*)d_out;
    const int nvis = in_sizes[uv_idx[0]];

    // Same output-mode logic that passed in R4/R5.
    int mode = (out_size >= 2 * nvis) ? 1 : 0;

    prep_kernel<<<(NPIX * NPIX + 255) / 256, 256>>>(base);
    int bx = (nvis + TPB - 1) / TPB;       // 143 for nvis=50000
    dim3 grid(bx, 2);                      // 286 CTAs = 2/SM, single wave
    vis_kernel<<<grid, TPB>>>(uu, vv, nvis);
    combine_kernel<<<(nvis + 255) / 256, 256>>>(uu, vv, out, nvis, mode);
}

// round 8
// speedup vs baseline: 1.2374x; 1.0378x over previous
#include <cuda_runtime.h>
#include <math.h>

#define NPIX 256
#define TPB 256          // 2 vis/thread; grid (98,3) = 294 CTAs ~= 2/SM single wave
#define YTILE 32
#define GRIDX 98
#define KSTRIDE (GRIDX * TPB)        // 25088
#define KMAX (2 * KSTRIDE)           // 50176 vis slots

// Preprocessed image (softplus + 3x3 Hann conv), row-major.
__device__ __align__(16) float d_img[NPIX * NPIX];
// Partial sums per y-third: d_part[part][k] = (re, im) before centering/scale
__device__ __align__(16) float2 d_part[3][KMAX];

// Kernel 1: img = HannConv3x3(softplus(base)), zero-padded SAME.
__global__ void prep_kernel(const float* __restrict__ base) {
    int idx = blockIdx.x * blockDim.x + threadIdx.x;
    if (idx >= NPIX * NPIX) return;
    int px = idx & (NPIX - 1);
    int py = idx >> 8;
    const float w[3] = {0.25f, 0.5f, 0.25f};
    float acc = 0.f;
#pragma unroll
    for (int dy = -1; dy <= 1; ++dy) {
#pragma unroll
        for (int dx = -1; dx <= 1; ++dx) {
            int yy = py + dy, xx = px + dx;
            if (yy >= 0 && yy < NPIX && xx >= 0 && xx < NPIX) {
                float v = base[yy * NPIX + xx];
                float sp = fmaxf(v, 0.f) + log1pf(expf(-fabsf(v)));  // stable softplus
                acc += w[dy + 1] * w[dx + 1] * sp;
            }
        }
    }
    d_img[idx] = acc;
}

// Kernel 2: exact type-2 NUDFT partial over one y-third, 2 visibilities/thread.
// d_part[part][k] = sum_{y in part} e^{-2pi*i*fv*y} sum_x img[y,x] e^{-2pi*i*fu*x}
__global__ void __launch_bounds__(TPB, 2)
vis_kernel(const float* __restrict__ uu,
           const float* __restrict__ vv, int nvis) {
    __shared__ __align__(16) float st[YTILE * NPIX];   // 32 KB, row-major tile

    const int tid  = threadIdx.x;
    const int part = blockIdx.y;
    const int k0 = blockIdx.x * TPB + tid;
    const int k1 = k0 + KSTRIDE;
    const float ARCSEC_F = (float)(M_PI / 180.0 / 3600.0);
    const float cell_rad = 0.005f * ARCSEC_F;

    float fu0 = 0.f, fv0 = 0.f, fu1 = 0.f, fv1 = 0.f;
    if (k0 < nvis) { fu0 = (uu[k0] * 1e3f) * cell_rad; fv0 = (vv[k0] * 1e3f) * cell_rad; }
    if (k1 < nvis) { fu1 = (uu[k1] * 1e3f) * cell_rad; fv1 = (vv[k1] * 1e3f) * cell_rad; }

    // x-twiddle tables wt[r] = w^r (r=0..15) for each visibility.
    float wt0r[16], wt0i[16], wt1r[16], wt1i[16];
    {
        float cr, ci;
        sincospif(-2.f * fu0, &ci, &cr);
        wt0r[0] = 1.f; wt0i[0] = 0.f;
#pragma unroll
        for (int r = 1; r < 16; ++r) {
            wt0r[r] = wt0r[r-1] * cr - wt0i[r-1] * ci;
            wt0i[r] = wt0r[r-1] * ci + wt0i[r-1] * cr;
        }
        sincospif(-2.f * fu1, &ci, &cr);
        wt1r[0] = 1.f; wt1i[0] = 0.f;
#pragma unroll
        for (int r = 1; r < 16; ++r) {
            wt1r[r] = wt1r[r-1] * cr - wt1i[r-1] * ci;
            wt1i[r] = wt1r[r-1] * ci + wt1i[r-1] * cr;
        }
    }
    // W16 = w^16 (exact seeds)
    float W0r, W0i; sincospif(-32.f * fu0, &W0i, &W0r);
    float W1r, W1i; sincospif(-32.f * fu1, &W1i, &W1r);
    // y-phase steps wv = exp(-2*pi*i*fv)
    float wv0r, wv0i; sincospif(-2.f * fv0, &wv0i, &wv0r);
    float wv1r, wv1i; sincospif(-2.f * fv1, &wv1i, &wv1r);

    float v0r = 0.f, v0i = 0.f, v1r = 0.f, v1i = 0.f;

    const int ybeg = (NPIX * part) / 3;
    const int yend = (NPIX * (part + 1)) / 3;

    for (int y0 = ybeg; y0 < yend; y0 += YTILE) {
        const int rows = min(YTILE, yend - y0);
        __syncthreads();
        {
            const float4* src = (const float4*)(d_img + y0 * NPIX);
            float4* dst = (float4*)st;
            for (int i = tid; i < rows * (NPIX / 4); i += TPB) dst[i] = src[i];
        }
        __syncthreads();

        // b seeds: b_y0 = exp(-2*pi*i*fv*y0), exact reseed per tile (no drift)
        float b0r, b0i; sincospif(-2.f * fv0 * (float)y0, &b0i, &b0r);
        float b1r, b1i; sincospif(-2.f * fv1 * (float)y0, &b1i, &b1r);

        for (int j = 0; j < rows; ++j) {
            const float4* row = (const float4*)(st + j * NPIX);
            float r0r = 0.f, r0i = 0.f, r1r = 0.f, r1i = 0.f;   // row sums
            float A0r = 1.f, A0i = 0.f, A1r = 1.f, A1i = 0.f;   // W16^q

            for (int q = 0; q < 16; ++q) {        // rolled: table indices stay static
                float p0r = 0.f, p0i = 0.f, p1r = 0.f, p1i = 0.f;
#pragma unroll
                for (int m = 0; m < 4; ++m) {     // 4 float4 = 16 pixels
                    const float4 p = row[q * 4 + m];   // broadcast LDS.128, reused by BOTH vis
                    const int r = 4 * m;
                    p0r += p.x * wt0r[r+0]; p0i += p.x * wt0i[r+0];
                    p1r += p.x * wt1r[r+0]; p1i += p.x * wt1i[r+0];
                    p0r += p.y * wt0r[r+1]; p0i += p.y * wt0i[r+1];
                    p1r += p.y * wt1r[r+1]; p1i += p.y * wt1i[r+1];
                    p0r += p.z * wt0r[r+2]; p0i += p.z * wt0i[r+2];
                    p1r += p.z * wt1r[r+2]; p1i += p.z * wt1i[r+2];
                    p0r += p.w * wt0r[r+3]; p0i += p.w * wt0i[r+3];
                    p1r += p.w * wt1r[r+3]; p1i += p.w * wt1i[r+3];
                }
                // row += p * A ; A *= W16   (4+4 FFMA per vis)
                r0r += p0r * A0r - p0i * A0i;  r0i += p0r * A0i + p0i * A0r;
                r1r += p1r * A1r - p1i * A1i;  r1i += p1r * A1i + p1i * A1r;
                float t;
                t = A0r * W0r - A0i * W0i; A0i = A0r * W0i + A0i * W0r; A0r = t;
                t = A1r * W1r - A1i * W1i; A1i = A1r * W1i + A1i * W1r; A1r = t;
            }
            // vis += row * b ; b *= wv
            v0r += r0r * b0r - r0i * b0i;  v0i += r0r * b0i + r0i * b0r;
            v1r += r1r * b1r - r1i * b1i;  v1i += r1r * b1i + r1i * b1r;
            float t;
            t = b0r * wv0r - b0i * wv0i; b0i = b0r * wv0i + b0i * wv0r; b0r = t;
            t = b1r * wv1r - b1i * wv1i; b1i = b1r * wv1i + b1i * wv1r; b1r = t;
        }
    }

    if (k0 < nvis) d_part[part][k0] = make_float2(v0r, v0i);
    if (k1 < nvis) d_part[part][k1] = make_float2(v1r, v1i);
}

// Kernel 3: combine thirds, apply centering phase and pixel solid angle.
__global__ void combine_kernel(const float* __restrict__ uu,
                               const float* __restrict__ vv,
                               float* __restrict__ out, int nvis, int mode) {
    int k = blockIdx.x * blockDim.x + threadIdx.x;
    if (k >= nvis) return;
    const float ARCSEC_F = (float)(M_PI / 180.0 / 3600.0);
    const float cell_rad = 0.005f * ARCSEC_F;
    float fu = (uu[k] * 1e3f) * cell_rad;
    float fv = (vv[k] * 1e3f) * cell_rad;
    float2 p0 = d_part[0][k];
    float2 p1 = d_part[1][k];
    float2 p2 = d_part[2][k];
    float visr = p0.x + p1.x + p2.x;
    float visi = p0.y + p1.y + p2.y;
    // centering phase: exp(+2*pi*i*128*(fu+fv)) — exact, applied once
    float Sr, Si; sincospif(256.f * fu + 256.f * fv, &Si, &Sr);
    float c2 = cell_rad * cell_rad;
    float orr = (visr * Sr - visi * Si) * c2;
    float oii = (visr * Si + visi * Sr) * c2;
    if (mode == 0) {
        out[k] = orr;
    } else {
        out[2 * k + 0] = orr;
        out[2 * k + 1] = oii;
    }
}

extern "C" void kernel_launch(void* const* d_in, const int* in_sizes, int n_in,
                              void* d_out, int out_size) {
    // Input mapping by size: image is uniquely the 65536-element input;
    // the remaining two, in order, are uu then vv.
    int img_i = -1;
    for (int i = 0; i < n_in; ++i)
        if (in_sizes[i] == NPIX * NPIX) { img_i = i; break; }
    if (img_i < 0) img_i = 0;
    int uv_idx[2]; int c = 0;
    for (int i = 0; i < n_in && c < 2; ++i)
        if (i != img_i) uv_idx[c++] = i;

    const float* base = (const float*)d_in[img_i];
    const float* uu   = (const float*)d_in[uv_idx[0]];
    const float* vv   = (const float*)d_in[uv_idx[1]];
    float* out = (float*)d_out;
    const int nvis = in_sizes[uv_idx[0]];

    // Same output-mode logic that passed in R4-R7.
    int mode = (out_size >= 2 * nvis) ? 1 : 0;

    prep_kernel<<<(NPIX * NPIX + 255) / 256, 256>>>(base);
    dim3 grid(GRIDX, 3);                 // 294 CTAs, 2/SM, single wave
    vis_kernel<<<grid, TPB>>>(uu, vv, nvis);
    combine_kernel<<<(nvis + 255) / 256, 256>>>(uu, vv, out, nvis, mode);
}

// round 9
// speedup vs baseline: 5.1560x; 4.1669x over previous
#include <cuda_runtime.h>
#include <math.h>

#define NPIX 256
#define NFFT 512
#define KBW  8           // kernel width (fine-grid cells)
#define KBHALF 4
#define KBBETA (2.30f * KBW)

// Scratch (all __device__ globals; no allocations)
__device__ __align__(16) float  d_img[NPIX * NPIX];     // softplus+conv image
__device__ float  d_dpd[NPIX];                           // 1D deapodization psi((x-128)/512)
__device__ __align__(16) float2 d_R[NPIX * NFFT];        // row FFTs: R[y][mu]
__device__ __align__(16) float2 d_F[NFFT * NFFT];        // full spectrum F[mv][mu]

// ---------- Kernel 1: softplus + 3x3 Hann conv ----------
__global__ void prep_kernel(const float* __restrict__ base) {
    int idx = blockIdx.x * blockDim.x + threadIdx.x;
    if (idx >= NPIX * NPIX) return;
    int px = idx & (NPIX - 1);
    int py = idx >> 8;
    const float w[3] = {0.25f, 0.5f, 0.25f};
    float acc = 0.f;
#pragma unroll
    for (int dy = -1; dy <= 1; ++dy) {
#pragma unroll
        for (int dx = -1; dx <= 1; ++dx) {
            int yy = py + dy, xx = px + dx;
            if (yy >= 0 && yy < NPIX && xx >= 0 && xx < NPIX) {
                float v = base[yy * NPIX + xx];
                float sp = fmaxf(v, 0.f) + log1pf(expf(-fabsf(v)));
                acc += w[dy + 1] * w[dx + 1] * sp;
            }
        }
    }
    d_img[idx] = acc;
}

// ---------- ES spreading kernel ----------
__device__ __forceinline__ float es_phi(float z) {
    float t = 1.f - z * z * (1.f / (KBHALF * KBHALF));
    return expf(KBBETA * (sqrtf(fmaxf(t, 0.f)) - 1.f));
}

// ---------- Kernel 2: deapodization table ----------
// psi(xi) = int_{-4}^{4} phi(z) cos(2 pi xi z) dz, xi = (x-128)/512, trapezoid 512 intervals.
__global__ void dpd_kernel() {
    int x = threadIdx.x;              // 256 threads
    float xi = (float)(x - NPIX / 2) / (float)NFFT;
    const int NQ = 512;
    const float h = (2.f * KBHALF) / NQ;
    float s = 0.f;
    for (int i = 0; i <= NQ; ++i) {
        float z = -KBHALF + h * i;
        float c; // cos(2*pi*xi*z) = cospi(2*xi*z)
        c = cospif(2.f * xi * z);
        float p = es_phi(z);
        float wgt = (i == 0 || i == NQ) ? 0.5f : 1.f;
        s += wgt * p * c;
    }
    d_dpd[x] = s * h;
}

// ---------- Stockham radix-2 512-pt FFT in shared memory ----------
// 256 threads; in/out through float2 smem buffers. Forward DFT: e^{-2pi i mk/N}.
__device__ __forceinline__ void fft512(float2* bufA, float2* bufB, int tid) {
    float2 *src = bufA, *dst = bufB;
#pragma unroll
    for (int s = 0, L = 1; s < 9; ++s, L <<= 1) {
        __syncthreads();
        int j = tid;                   // 0..255
        int kk = j & (L - 1);
        float wr, wi; sincospif(-(float)kk / (float)L, &wi, &wr);  // exp(-i pi k / L)
        float2 a = src[j], b = src[j + 256];
        float tbr = b.x * wr - b.y * wi;
        float tbi = b.x * wi + b.y * wr;
        dst[2 * j - kk]     = make_float2(a.x + tbr, a.y + tbi);
        dst[2 * j - kk + L] = make_float2(a.x - tbr, a.y - tbi);
        float2* tmp = src; src = dst; dst = tmp;
    }
    __syncthreads();
    // result is in src == bufB after 9 stages (odd count). Callers read bufB.
}

// ---------- Kernel 3: row FFTs ----------
// CTA y: load deapodized row with centered placement j=(x-128)mod512, FFT, store R[y][*].
__global__ void __launch_bounds__(256) fft_rows_kernel() {
    __shared__ float2 bufA[NFFT], bufB[NFFT];
    int y = blockIdx.x;
    int tid = threadIdx.x;
    float dy = 1.f / d_dpd[y];
#pragma unroll
    for (int h = 0; h < 2; ++h) {
        int j = tid + h * 256;
        float re = 0.f;
        int x = -1;
        if (j < 128) x = j + 128;
        else if (j >= 384) x = j - 384;
        if (x >= 0) re = d_img[y * NPIX + x] * dy / d_dpd[x];
        bufA[j] = make_float2(re, 0.f);
    }
    fft512(bufA, bufB, tid);
    d_R[y * NFFT + tid]       = bufB[tid];
    d_R[y * NFFT + tid + 256] = bufB[tid + 256];
}

// ---------- Kernel 4: column FFTs ----------
// CTA mu: load R[y][mu] with centered placement j=(y-128)mod512, FFT, store F[mv][mu].
__global__ void __launch_bounds__(256) fft_cols_kernel() {
    __shared__ float2 bufA[NFFT], bufB[NFFT];
    int mu = blockIdx.x;
    int tid = threadIdx.x;
#pragma unroll
    for (int h = 0; h < 2; ++h) {
        int j = tid + h * 256;
        float2 v = make_float2(0.f, 0.f);
        int y = -1;
        if (j < 128) y = j + 128;
        else if (j >= 384) y = j - 384;
        if (y >= 0) v = d_R[y * NFFT + mu];
        bufA[j] = v;
    }
    fft512(bufA, bufB, tid);
    d_F[(tid) * NFFT + mu]       = bufB[tid];
    d_F[(tid + 256) * NFFT + mu] = bufB[tid + 256];
}

// ---------- Kernel 5: per-visibility 8x8 interpolation ----------
__global__ void interp_kernel(const float* __restrict__ uu,
                              const float* __restrict__ vv,
                              float* __restrict__ out, int nvis, int mode) {
    int k = blockIdx.x * blockDim.x + threadIdx.x;
    if (k >= nvis) return;
    const float ARCSEC_F = (float)(M_PI / 180.0 / 3600.0);
    const float cell_rad = 0.005f * ARCSEC_F;
    float fu = (uu[k] * 1e3f) * cell_rad;   // cycles/pixel, |fu| <= 0.25
    float fv = (vv[k] * 1e3f) * cell_rad;
    float gu = (float)NFFT * fu;            // fine-grid coordinate
    float gv = (float)NFFT * fv;
    int bu = (int)floorf(gu);
    int bv = (int)floorf(gv);

    float wu[KBW], wv[KBW];
#pragma unroll
    for (int t = 0; t < KBW; ++t) {
        wu[t] = es_phi(gu - (float)(bu - 3 + t));
        wv[t] = es_phi(gv - (float)(bv - 3 + t));
    }

    float vr = 0.f, vi = 0.f;
#pragma unroll
    for (int tv = 0; tv < KBW; ++tv) {
        int mv = (bv - 3 + tv) & (NFFT - 1);
        const float2* Frow = &d_F[mv * NFFT];
        float rr = 0.f, ri = 0.f;
#pragma unroll
        for (int tu = 0; tu < KBW; ++tu) {
            int mu = (bu - 3 + tu) & (NFFT - 1);
            float2 f = Frow[mu];
            rr += wu[tu] * f.x;
            ri += wu[tu] * f.y;
        }
        vr += wv[tv] * rr;
        vi += wv[tv] * ri;
    }

    float c2 = cell_rad * cell_rad;
    float orr = vr * c2;
    float oii = vi * c2;
    if (mode == 0) {
        out[k] = orr;
    } else {
        out[2 * k + 0] = orr;
        out[2 * k + 1] = oii;
    }
}

extern "C" void kernel_launch(void* const* d_in, const int* in_sizes, int n_in,
                              void* d_out, int out_size) {
    // Input mapping by size (proven R4-R8): image is the 65536-element input;
    // the remaining two, in order, are uu then vv.
    int img_i = -1;
    for (int i = 0; i < n_in; ++i)
        if (in_sizes[i] == NPIX * NPIX) { img_i = i; break; }
    if (img_i < 0) img_i = 0;
    int uv_idx[2]; int c = 0;
    for (int i = 0; i < n_in && c < 2; ++i)
        if (i != img_i) uv_idx[c++] = i;

    const float* base = (const float*)d_in[img_i];
    const float* uu   = (const float*)d_in[uv_idx[0]];
    const float* vv   = (const float*)d_in[uv_idx[1]];
    float* out = (float*)d_out;
    const int nvis = in_sizes[uv_idx[0]];

    // Output-mode logic (proven R4-R8).
    int mode = (out_size >= 2 * nvis) ? 1 : 0;

    prep_kernel<<<(NPIX * NPIX + 255) / 256, 256>>>(base);
    dpd_kernel<<<1, NPIX>>>();
    fft_rows_kernel<<<NPIX, 256>>>();
    fft_cols_kernel<<<NFFT, 256>>>();
    interp_kernel<<<(nvis + 255) / 256, 256>>>(uu, vv, out, nvis, mode);
}

// round 10
// speedup vs baseline: 18.5400x; 3.5958x over previous
#include <cuda_runtime.h>
#include <math.h>

#define NPIX 256
#define NFFT 512
#define KBW  6            // ES kernel width (fine-grid cells)
#define KBHALF 3
#define KBBETA (2.30f * KBW)
#define MUOFF 132         // fft_cols covers mu_signed in [-132, 131]
#define NMU   264

// Scratch (__device__ globals; no allocations)
__device__ float d_invd[NPIX];                           // 1/psi((x-128)/512)
__device__ __align__(16) float2 d_R[NPIX * NFFT];        // row FFTs: R[y][mu]
__device__ __align__(16) float2 d_F[NFFT * NFFT];        // spectrum, TRANSPOSED: F[mu][mv]

// ---------- ES spreading kernel ----------
__device__ __forceinline__ float es_phi(float z) {
    float t = 1.f - z * z * (1.f / (KBHALF * KBHALF));
    return expf(KBBETA * (sqrtf(fmaxf(t, 0.f)) - 1.f));
}

// ---------- Kernel A: deapodization table (parallel: 1 block per x) ----------
// psi(xi) = int_{-3}^{3} phi(z) cos(2 pi xi z) dz, xi=(x-128)/512, trapezoid 512 intervals.
__global__ void __launch_bounds__(128) dpd_kernel() {
    __shared__ float red[128];
    const int x = blockIdx.x;
    const int tid = threadIdx.x;
    const float xi = (float)(x - NPIX / 2) / (float)NFFT;
    const int NQ = 512;
    const float h = (2.f * KBHALF) / NQ;
    float s = 0.f;
    for (int i = tid; i <= NQ; i += 128) {
        float z = -KBHALF + h * i;
        float c = cospif(2.f * xi * z);
        float wgt = (i == 0 || i == NQ) ? 0.5f : 1.f;
        s += wgt * es_phi(z) * c;
    }
    red[tid] = s;
    __syncthreads();
    for (int d = 64; d > 0; d >>= 1) {
        if (tid < d) red[tid] += red[tid + d];
        __syncthreads();
    }
    if (tid == 0) d_invd[x] = 1.f / (red[0] * h);
}

// ---------- Stockham radix-2 512-pt FFT, twiddles from smem table ----------
// tw[m] = exp(-i*pi*m/256), m=0..255. Result ends in bufB.
__device__ __forceinline__ void fft512(float2* bufA, float2* bufB,
                                       const float2* tw, int tid) {
    float2 *src = bufA, *dst = bufB;
#pragma unroll
    for (int s = 0; s < 9; ++s) {
        const int L = 1 << s;
        __syncthreads();
        int kk = tid & (L - 1);
        float2 w = tw[kk << (8 - s)];
        float2 a = src[tid], b = src[tid + 256];
        float tbr = b.x * w.x - b.y * w.y;
        float tbi = b.x * w.y + b.y * w.x;
        dst[2 * tid - kk]     = make_float2(a.x + tbr, a.y + tbi);
        dst[2 * tid - kk + L] = make_float2(a.x - tbr, a.y - tbi);
        float2* tmp = src; src = dst; dst = tmp;
    }
    __syncthreads();
}

// ---------- Kernel B: fused softplus + Hann conv + deapodize + row FFT ----------
// CTA y: build deapodized row in centered placement j=(x-128)mod512, FFT, store R[y][*].
__global__ void __launch_bounds__(256) fft_rows_kernel(const float* __restrict__ base) {
    __shared__ float2 bufA[NFFT], bufB[NFFT];
    __shared__ float2 tw[256];
    __shared__ float sp[3][NPIX];
    const int y = blockIdx.x;
    const int tid = threadIdx.x;

    // twiddle table
    float twr, twi; sincospif(-(float)tid / 256.f, &twi, &twr);
    tw[tid] = make_float2(twr, twi);

    // softplus of the 3 needed base rows
#pragma unroll
    for (int d = 0; d < 3; ++d) {
        int yy = y - 1 + d;
        float v = 0.f;
        if (yy >= 0 && yy < NPIX) {
            float b = base[yy * NPIX + tid];
            v = fmaxf(b, 0.f) + log1pf(expf(-fabsf(b)));
        } else {
            v = -1.f;   // marker: row out of range -> contributes 0
        }
        sp[d][tid] = (yy >= 0 && yy < NPIX) ? v : 0.f;
    }
    __syncthreads();

    // 3x3 Hann conv at (y, x=tid), zero-padded
    float acc = 0.f;
    {
        const float hy[3] = {0.25f, 0.5f, 0.25f};
#pragma unroll
        for (int d = 0; d < 3; ++d) {
            float l = (tid > 0)        ? sp[d][tid - 1] : 0.f;
            float m = sp[d][tid];
            float r = (tid < NPIX - 1) ? sp[d][tid + 1] : 0.f;
            acc += hy[d] * (0.25f * l + 0.5f * m + 0.25f * r);
        }
    }
    float val = acc * d_invd[y] * d_invd[tid];

    // centered placement + zero middle band
    int j = (tid >= 128) ? (tid - 128) : (tid + 384);
    bufA[128 + tid] = make_float2(0.f, 0.f);
    __syncthreads();           // (paranoia: ordering of zero vs val writes is disjoint)
    bufA[j] = make_float2(val, 0.f);

    fft512(bufA, bufB, tw, tid);
    d_R[y * NFFT + tid]       = bufB[tid];
    d_R[y * NFFT + tid + 256] = bufB[tid + 256];
}

// ---------- Kernel C: column FFTs, only needed mu; TRANSPOSED coalesced store ----------
__global__ void __launch_bounds__(256) fft_cols_kernel() {
    __shared__ float2 bufA[NFFT], bufB[NFFT];
    __shared__ float2 tw[256];
    const int tid = threadIdx.x;
    const int mu = (blockIdx.x - MUOFF) & (NFFT - 1);

    float twr, twi; sincospif(-(float)tid / 256.f, &twi, &twr);
    tw[tid] = make_float2(twr, twi);

    // load column mu of R with centered placement j=(y-128)mod512
    int j = (tid >= 128) ? (tid - 128) : (tid + 384);
    bufA[128 + tid] = make_float2(0.f, 0.f);
    __syncthreads();
    bufA[j] = d_R[tid * NFFT + mu];

    fft512(bufA, bufB, tw, tid);
    // transposed store: F[mu][mv], mv contiguous -> coalesced
    d_F[mu * NFFT + tid]       = bufB[tid];
    d_F[mu * NFFT + tid + 256] = bufB[tid + 256];
}

// ---------- Kernel D: per-visibility 6x6 interpolation ----------
__global__ void interp_kernel(const float* __restrict__ uu,
                              const float* __restrict__ vv,
                              float* __restrict__ out, int nvis, int mode) {
    int k = blockIdx.x * blockDim.x + threadIdx.x;
    if (k >= nvis) return;
    const float ARCSEC_F = (float)(M_PI / 180.0 / 3600.0);
    const float cell_rad = 0.005f * ARCSEC_F;
    float fu = (uu[k] * 1e3f) * cell_rad;   // cycles/pixel, |fu| <= 0.25
    float fv = (vv[k] * 1e3f) * cell_rad;
    float gu = (float)NFFT * fu;            // fine-grid coordinate
    float gv = (float)NFFT * fv;
    int bu = (int)floorf(gu);
    int bv = (int)floorf(gv);

    float wu[KBW], wv[KBW];
#pragma unroll
    for (int t = 0; t < KBW; ++t) {
        wu[t] = es_phi(gu - (float)(bu - 2 + t));
        wv[t] = es_phi(gv - (float)(bv - 2 + t));
    }

    float vr = 0.f, vi = 0.f;
#pragma unroll
    for (int tu = 0; tu < KBW; ++tu) {
        int mu = (bu - 2 + tu) & (NFFT - 1);
        const float2* Fcol = &d_F[mu * NFFT];   // mv contiguous
        float rr = 0.f, ri = 0.f;
#pragma unroll
        for (int tv = 0; tv < KBW; ++tv) {
            int mv = (bv - 2 + tv) & (NFFT - 1);
            float2 f = Fcol[mv];
            rr += wv[tv] * f.x;
            ri += wv[tv] * f.y;
        }
        vr += wu[tu] * rr;
        vi += wu[tu] * ri;
    }

    float c2 = cell_rad * cell_rad;
    float orr = vr * c2;
    float oii = vi * c2;
    if (mode == 0) {
        out[k] = orr;
    } else {
        out[2 * k + 0] = orr;
        out[2 * k + 1] = oii;
    }
}

extern "C" void kernel_launch(void* const* d_in, const int* in_sizes, int n_in,
                              void* d_out, int out_size) {
    // Input mapping by size (proven R4-R9): image is the 65536-element input;
    // the remaining two, in order, are uu then vv.
    int img_i = -1;
    for (int i = 0; i < n_in; ++i)
        if (in_sizes[i] == NPIX * NPIX) { img_i = i; break; }
    if (img_i < 0) img_i = 0;
    int uv_idx[2]; int c = 0;
    for (int i = 0; i < n_in && c < 2; ++i)
        if (i != img_i) uv_idx[c++] = i;

    const float* base = (const float*)d_in[img_i];
    const float* uu   = (const float*)d_in[uv_idx[0]];
    const float* vv   = (const float*)d_in[uv_idx[1]];
    float* out = (float*)d_out;
    const int nvis = in_sizes[uv_idx[0]];

    // Output-mode logic (proven R4-R9).
    int mode = (out_size >= 2 * nvis) ? 1 : 0;

    dpd_kernel<<<NPIX, 128>>>();
    fft_rows_kernel<<<NPIX, 256>>>(base);
    fft_cols_kernel<<<NMU, 256>>>();
    interp_kernel<<<(nvis + 255) / 256, 256>>>(uu, vv, out, nvis, mode);
}

// round 11
// speedup vs baseline: 18.7664x; 1.0122x over previous
#include <cuda_runtime.h>
#include <math.h>

#define NPIX 256
#define NFFT 512
#define KBW  6            // ES kernel width (fine-grid cells)
#define KBHALF 3
#define KBBETA (2.30f * KBW)
#define MUOFF 132         // fft_cols covers mu_signed in [-132, 131]
#define NMU   264

// Scratch (__device__ globals; no allocations)
__device__ float d_invd[NPIX];                           // 1/psi((x-128)/512)
__device__ __align__(16) float2 d_R[NPIX * NFFT];        // row FFTs: R[y][mu]
__device__ __align__(16) float2 d_F[NFFT * NFFT];        // spectrum, TRANSPOSED: F[mu][mv]

// ---------- ES spreading kernel ----------
__device__ __forceinline__ float es_phi(float z) {
    float t = 1.f - z * z * (1.f / (KBHALF * KBHALF));
    return expf(KBBETA * (sqrtf(fmaxf(t, 0.f)) - 1.f));
}

// ---------- Kernel A: deapodization table (1 block per x) ----------
__global__ void __launch_bounds__(128) dpd_kernel() {
    __shared__ float red[128];
    const int x = blockIdx.x;
    const int tid = threadIdx.x;
    const float xi = (float)(x - NPIX / 2) / (float)NFFT;
    const int NQ = 512;
    const float h = (2.f * KBHALF) / NQ;
    float s = 0.f;
    for (int i = tid; i <= NQ; i += 128) {
        float z = -KBHALF + h * i;
        float c = cospif(2.f * xi * z);
        float wgt = (i == 0 || i == NQ) ? 0.5f : 1.f;
        s += wgt * es_phi(z) * c;
    }
    red[tid] = s;
    __syncthreads();
    for (int d = 64; d > 0; d >>= 1) {
        if (tid < d) red[tid] += red[tid + d];
        __syncthreads();
    }
    if (tid == 0) d_invd[x] = 1.f / (red[0] * h);
}

// ---------- Stockham radix-2 512-pt FFT, twiddles from smem table ----------
// tw[m] = exp(-i*pi*m/256), m=0..255. Result ends in bufB.
__device__ __forceinline__ void fft512(float2* bufA, float2* bufB,
                                       const float2* tw, int tid) {
    float2 *src = bufA, *dst = bufB;
#pragma unroll
    for (int s = 0; s < 9; ++s) {
        const int L = 1 << s;
        __syncthreads();
        int kk = tid & (L - 1);
        float2 w = tw[kk << (8 - s)];
        float2 a = src[tid], b = src[tid + 256];
        float tbr = b.x * w.x - b.y * w.y;
        float tbi = b.x * w.y + b.y * w.x;
        dst[2 * tid - kk]     = make_float2(a.x + tbr, a.y + tbi);
        dst[2 * tid - kk + L] = make_float2(a.x - tbr, a.y - tbi);
        float2* tmp = src; src = dst; dst = tmp;
    }
    __syncthreads();
}

// ---------- Kernel B: fused softplus + Hann conv + deapodize + row FFT ----------
__global__ void __launch_bounds__(256) fft_rows_kernel(const float* __restrict__ base) {
    __shared__ float2 bufA[NFFT], bufB[NFFT];
    __shared__ float2 tw[256];
    __shared__ float sp[3][NPIX];
    const int y = blockIdx.x;
    const int tid = threadIdx.x;

    float twr, twi; sincospif(-(float)tid / 256.f, &twi, &twr);
    tw[tid] = make_float2(twr, twi);

#pragma unroll
    for (int d = 0; d < 3; ++d) {
        int yy = y - 1 + d;
        float v = 0.f;
        if (yy >= 0 && yy < NPIX) {
            float b = base[yy * NPIX + tid];
            v = fmaxf(b, 0.f) + log1pf(expf(-fabsf(b)));
        }
        sp[d][tid] = v;
    }
    __syncthreads();

    float acc = 0.f;
    {
        const float hy[3] = {0.25f, 0.5f, 0.25f};
#pragma unroll
        for (int d = 0; d < 3; ++d) {
            float l = (tid > 0)        ? sp[d][tid - 1] : 0.f;
            float m = sp[d][tid];
            float r = (tid < NPIX - 1) ? sp[d][tid + 1] : 0.f;
            acc += hy[d] * (0.25f * l + 0.5f * m + 0.25f * r);
        }
    }
    float val = acc * d_invd[y] * d_invd[tid];

    int j = (tid >= 128) ? (tid - 128) : (tid + 384);
    bufA[128 + tid] = make_float2(0.f, 0.f);
    __syncthreads();
    bufA[j] = make_float2(val, 0.f);

    fft512(bufA, bufB, tw, tid);
    d_R[y * NFFT + tid]       = bufB[tid];
    d_R[y * NFFT + tid + 256] = bufB[tid + 256];
}

// ---------- Kernel C: column FFTs, only needed mu; TRANSPOSED coalesced store ----------
__global__ void __launch_bounds__(256) fft_cols_kernel() {
    __shared__ float2 bufA[NFFT], bufB[NFFT];
    __shared__ float2 tw[256];
    const int tid = threadIdx.x;
    const int mu = (blockIdx.x - MUOFF) & (NFFT - 1);

    float twr, twi; sincospif(-(float)tid / 256.f, &twi, &twr);
    tw[tid] = make_float2(twr, twi);

    int j = (tid >= 128) ? (tid - 128) : (tid + 384);
    bufA[128 + tid] = make_float2(0.f, 0.f);
    __syncthreads();
    bufA[j] = d_R[tid * NFFT + mu];

    fft512(bufA, bufB, tw, tid);
    d_F[mu * NFFT + tid]       = bufB[tid];
    d_F[mu * NFFT + tid + 256] = bufB[tid + 256];
}

// ---------- Kernel D: cooperative 8-lanes-per-visibility 6x6 interpolation ----------
// lane t in [0,6): handles tap column tu=t (mv-contiguous loads from transposed F);
// 3 shfl rounds reduce the 8-lane group; lane 0 writes.
__global__ void __launch_bounds__(256) interp_kernel(const float* __restrict__ uu,
                              const float* __restrict__ vv,
                              float* __restrict__ out, int nvis, int mode) {
    const int tid  = threadIdx.x;
    const int lane = tid & 7;                      // lane within 8-lane group
    const int k    = blockIdx.x * 32 + (tid >> 3); // 32 visibilities per CTA

    float vr = 0.f, vi = 0.f;
    float fu = 0.f, fv = 0.f;
    const float ARCSEC_F = (float)(M_PI / 180.0 / 3600.0);
    const float cell_rad = 0.005f * ARCSEC_F;

    if (k < nvis) {
        fu = (uu[k] * 1e3f) * cell_rad;            // |fu| <= 0.25
        fv = (vv[k] * 1e3f) * cell_rad;
        float gu = (float)NFFT * fu;
        float gv = (float)NFFT * fv;
        int bu = (int)floorf(gu);
        int bv = (int)floorf(gv);

        if (lane < KBW) {
            // own u-tap weight
            float wu = es_phi(gu - (float)(bu - 2 + lane));
            // v-tap weights (same for all lanes in group)
            float wv[KBW];
#pragma unroll
            for (int t = 0; t < KBW; ++t)
                wv[t] = es_phi(gv - (float)(bv - 2 + t));

            int mu = (bu - 2 + lane) & (NFFT - 1);
            const float2* Fcol = &d_F[mu * NFFT];  // mv contiguous
            float rr = 0.f, ri = 0.f;
#pragma unroll
            for (int t = 0; t < KBW; ++t) {
                int mv = (bv - 2 + t) & (NFFT - 1);
                float2 f = __ldg(&Fcol[mv]);
                rr += wv[t] * f.x;
                ri += wv[t] * f.y;
            }
            vr = wu * rr;
            vi = wu * ri;
        }
    }

    // reduce the 8-lane group
#pragma unroll
    for (int off = 4; off > 0; off >>= 1) {
        vr += __shfl_down_sync(0xffffffffu, vr, off, 8);
        vi += __shfl_down_sync(0xffffffffu, vi, off, 8);
    }

    if (lane == 0 && k < nvis) {
        float c2 = cell_rad * cell_rad;
        float orr = vr * c2;
        float oii = vi * c2;
        if (mode == 0) {
            out[k] = orr;
        } else {
            out[2 * k + 0] = orr;
            out[2 * k + 1] = oii;
        }
    }
}

extern "C" void kernel_launch(void* const* d_in, const int* in_sizes, int n_in,
                              void* d_out, int out_size) {
    // Input mapping by size (proven R4-R10): image is the 65536-element input;
    // the remaining two, in order, are uu then vv.
    int img_i = -1;
    for (int i = 0; i < n_in; ++i)
        if (in_sizes[i] == NPIX * NPIX) { img_i = i; break; }
    if (img_i < 0) img_i = 0;
    int uv_idx[2]; int c = 0;
    for (int i = 0; i < n_in && c < 2; ++i)
        if (i != img_i) uv_idx[c++] = i;

    const float* base = (const float*)d_in[img_i];
    const float* uu   = (const float*)d_in[uv_idx[0]];
    const float* vv   = (const float*)d_in[uv_idx[1]];
    float* out = (float*)d_out;
    const int nvis = in_sizes[uv_idx[0]];

    // Output-mode logic (proven R4-R10).
    int mode = (out_size >= 2 * nvis) ? 1 : 0;

    dpd_kernel<<<NPIX, 128>>>();
    fft_rows_kernel<<<NPIX, 256>>>(base);
    fft_cols_kernel<<<NMU, 256>>>();
    interp_kernel<<<(nvis * 8 + 255) / 256, 256>>>(uu, vv, out, nvis, mode);
}